// round 9
// baseline (speedup 1.0000x reference)
#include <cuda_runtime.h>
#include <cuda_bf16.h>
#include <cuda_fp16.h>
#include <cstdint>
#include <cstddef>

#define NU 100000
#define NVV 100000
#define DD 128
#define RR 5
#define OO 64
#define EE 640000
#define NE_T (RR * EE)                 /* 3.2M edges per side */

#define GEMM_TILES 782                 /* ceil(100000/128) */

// ---------------------------------------------------------------------------
// Scratch (static device globals)
// ---------------------------------------------------------------------------
__device__ __half g_tmpU[(size_t)RR * NU * OO];   // [r][n][64] fp16
__device__ __half g_tmpV[(size_t)RR * NVV * OO];
__device__ unsigned char g_BimgU[RR * 32768];     // pre-swizzled bf16 hi/lo B
__device__ unsigned char g_BimgV[RR * 32768];

// CSR build: side 0 = z_u (keys sup_rows, gather tmpV), side 1 = z_v.
__device__ int   g_cnt[2][100000];
__device__ int   g_ptr[2][100001];
__device__ int   g_cur[2][100000];
__device__ uint2 g_payU[NE_T];   // {rel*100000+col, val bits}
__device__ uint2 g_payV[NE_T];

// ---------------------------------------------------------------------------
// helpers
// ---------------------------------------------------------------------------
__device__ __forceinline__ uint32_t smem_u32(const void* p) {
    uint32_t a;
    asm("{ .reg .u64 t; cvta.to.shared.u64 t, %1; cvt.u32.u64 %0, t; }"
        : "=r"(a) : "l"(p));
    return a;
}
__device__ __forceinline__ void ldsm4(uint32_t addr, uint32_t& r0, uint32_t& r1,
                                      uint32_t& r2, uint32_t& r3) {
    asm volatile("ldmatrix.sync.aligned.m8n8.x4.shared.b16 {%0,%1,%2,%3}, [%4];"
                 : "=r"(r0), "=r"(r1), "=r"(r2), "=r"(r3) : "r"(addr));
}
__device__ __forceinline__ void mma_bf16(float* d, const uint32_t* a,
                                         uint32_t b0, uint32_t b1) {
    asm volatile(
        "mma.sync.aligned.m16n8k16.row.col.f32.bf16.bf16.f32 "
        "{%0,%1,%2,%3}, {%4,%5,%6,%7}, {%8,%9}, {%0,%1,%2,%3};"
        : "+f"(d[0]), "+f"(d[1]), "+f"(d[2]), "+f"(d[3])
        : "r"(a[0]), "r"(a[1]), "r"(a[2]), "r"(a[3]), "r"(b0), "r"(b1));
}

// ---------------------------------------------------------------------------
// cumsum weights + pack swizzled bf16 hi/lo B images (k = d, n = o)
// ---------------------------------------------------------------------------
__global__ void cumsum_pack_kernel(const float* __restrict__ wu,
                                   const float* __restrict__ wv,
                                   unsigned char* __restrict__ imgU,
                                   unsigned char* __restrict__ imgV)
{
    int i = blockIdx.x * blockDim.x + threadIdx.x;
    if (i >= DD * OO) return;
    const float* w    = blockIdx.y ? wv : wu;
    unsigned char* im = blockIdx.y ? imgV : imgU;
    int k = i >> 6, n = i & 63;
    uint32_t off = (uint32_t)n * 256 + ((((k >> 3) ^ (n & 7))) << 4) + (k & 7) * 2;
    float s = 0.f;
#pragma unroll
    for (int r = 0; r < RR; r++) {
        s += w[r * DD * OO + i];
        __nv_bfloat16 h = __float2bfloat16_rn(s);
        __nv_bfloat16 l = __float2bfloat16_rn(s - __bfloat162float(h));
        *(__nv_bfloat16*)(im + r * 32768 + off)         = h;
        *(__nv_bfloat16*)(im + r * 32768 + 16384 + off) = l;
    }
}

// ---------------------------------------------------------------------------
// CSR build phase
// ---------------------------------------------------------------------------
__global__ void hist_kernel(const int* __restrict__ srow,
                            const int* __restrict__ scol)
{
    int e = blockIdx.x * 256 + threadIdx.x;
    if (e >= NE_T) return;
    atomicAdd(&g_cnt[0][__ldg(srow + e)], 1);
    atomicAdd(&g_cnt[1][__ldg(scol + e)], 1);
}

// one block (1024 thr) per side: exclusive scan of 100k counts
__global__ void __launch_bounds__(1024)
scan_kernel()
{
    const int side = blockIdx.x;
    const int* c = g_cnt[side];
    int* p  = g_ptr[side];
    int* cu = g_cur[side];
    __shared__ int sums[1024];
    const int t = threadIdx.x;
    const int CH = 98;                       // 1024*98 >= 100000
    int lo = t * CH, hi = lo + CH;
    if (hi > 100000) hi = 100000;
    int s = 0;
    for (int i = lo; i < hi; i++) s += c[i];
    sums[t] = s;
    __syncthreads();
    for (int off = 1; off < 1024; off <<= 1) {
        int v = sums[t];
        if (t >= off) v += sums[t - off];
        __syncthreads();
        sums[t] = v;
        __syncthreads();
    }
    int run = t ? sums[t - 1] : 0;
    for (int i = lo; i < hi; i++) {
        p[i] = run;
        cu[i] = run;
        run += c[i];
    }
    if (t == 1023) p[100000] = sums[1023];
}

__global__ void scatter_kernel(const int* __restrict__ srow,
                               const int* __restrict__ scol,
                               const float* __restrict__ sval)
{
    int e = blockIdx.x * 256 + threadIdx.x;
    if (e >= NE_T) return;
    int r = e / EE;
    int row = __ldg(srow + e);
    int col = __ldg(scol + e);
    uint32_t vb = __float_as_uint(__ldg(sval + e));
    int pu = atomicAdd(&g_cur[0][row], 1);
    g_payU[pu] = make_uint2((uint32_t)(r * 100000 + col), vb);
    int pv = atomicAdd(&g_cur[1][col], 1);
    g_payV[pv] = make_uint2((uint32_t)(r * 100000 + row), vb);
}

// ---------------------------------------------------------------------------
// GEMM: one CTA = 128-row tile, loops over all 5 relations (A loaded once).
// Split-bf16 3-pass, double-buffered fragments. 256 thr, warp tile 32x32.
// ---------------------------------------------------------------------------
#define OFF_AH 0
#define OFF_AL 32768
#define OFF_BH 65536
#define OFF_BL 81920
#define GT_SMEM 98304

__global__ void __launch_bounds__(256, 2)
gemm_tc_kernel(const float* __restrict__ A,
               const unsigned char* __restrict__ Bimg,
               __half* __restrict__ C, int M)
{
    extern __shared__ unsigned char smem[];
    const int tid  = threadIdx.x;
    const int wid  = tid >> 5;
    const int lane = tid & 31;
    const int m0   = blockIdx.x * 128;

    for (int idx = tid; idx < 2048; idx += 256) {
        int m = idx >> 4, c = idx & 15, k0 = c << 3;
        float4 v0 = make_float4(0, 0, 0, 0), v1 = make_float4(0, 0, 0, 0);
        if (m0 + m < M) {
            const float* ap = A + (size_t)(m0 + m) * DD + k0;
            v0 = *(const float4*)ap;
            v1 = *(const float4*)(ap + 4);
        }
        float f[8] = {v0.x, v0.y, v0.z, v0.w, v1.x, v1.y, v1.z, v1.w};
        uint32_t hi[4], lo[4];
#pragma unroll
        for (int j = 0; j < 4; j++) {
            __nv_bfloat16 h0 = __float2bfloat16_rn(f[2 * j]);
            __nv_bfloat16 h1 = __float2bfloat16_rn(f[2 * j + 1]);
            __nv_bfloat16 l0 = __float2bfloat16_rn(f[2 * j]     - __bfloat162float(h0));
            __nv_bfloat16 l1 = __float2bfloat16_rn(f[2 * j + 1] - __bfloat162float(h1));
            hi[j] = (uint32_t)__bfloat16_as_ushort(h0) | ((uint32_t)__bfloat16_as_ushort(h1) << 16);
            lo[j] = (uint32_t)__bfloat16_as_ushort(l0) | ((uint32_t)__bfloat16_as_ushort(l1) << 16);
        }
        uint32_t off = (uint32_t)m * 256 + ((c ^ (m & 7)) << 4);
        *(uint4*)(smem + OFF_AH + off) = make_uint4(hi[0], hi[1], hi[2], hi[3]);
        *(uint4*)(smem + OFF_AL + off) = make_uint4(lo[0], lo[1], lo[2], lo[3]);
    }

    const int mbase = (wid >> 1) * 32;
    const int nbase = (wid & 1) * 32;
    const uint32_t sb = smem_u32(smem);
    const int a_m  = mbase + (lane & 15);
    const int a_cb = lane >> 4;
    const int b_n  = nbase + (lane & 7) + ((lane >> 4) & 1) * 8;
    const int b_cb = (lane >> 3) & 1;
    const int grp4 = lane >> 2, tg = lane & 3;

    for (int g = 0; g < RR; g++) {
        {
            const uint4* src = (const uint4*)(Bimg + (size_t)g * 32768);
            uint4* dst = (uint4*)(smem + OFF_BH);
            for (int i = tid; i < 2048; i += 256) dst[i] = src[i];
        }
        __syncthreads();

        float acc[2][4][4];
#pragma unroll
        for (int i = 0; i < 2; i++)
#pragma unroll
            for (int j = 0; j < 4; j++)
#pragma unroll
                for (int q = 0; q < 4; q++) acc[i][j][q] = 0.f;

#pragma unroll
        for (int t = 0; t < 3; t++) {
            const uint32_t abase = sb + (t == 2 ? OFF_AL : OFF_AH);
            const uint32_t bbase = sb + (t == 1 ? OFF_BL : OFF_BH);
            uint32_t afr[2][2][4], bfr[2][2][4];
            auto load_frags = [&](int ks, int buf) {
                const int c = ks * 2;
#pragma unroll
                for (int mt = 0; mt < 2; mt++) {
                    int m = a_m + mt * 16, cc = c + a_cb;
                    uint32_t ad = abase + (uint32_t)m * 256 + ((cc ^ (m & 7)) << 4);
                    ldsm4(ad, afr[buf][mt][0], afr[buf][mt][1],
                              afr[buf][mt][2], afr[buf][mt][3]);
                }
#pragma unroll
                for (int pr = 0; pr < 2; pr++) {
                    int n = b_n + pr * 16, cc = c + b_cb;
                    uint32_t bd = bbase + (uint32_t)n * 256 + ((cc ^ (n & 7)) << 4);
                    ldsm4(bd, bfr[buf][pr][0], bfr[buf][pr][1],
                              bfr[buf][pr][2], bfr[buf][pr][3]);
                }
            };
            load_frags(0, 0);
#pragma unroll
            for (int ks = 0; ks < 8; ks++) {
                const int cur = ks & 1;
                if (ks < 7) load_frags(ks + 1, cur ^ 1);
#pragma unroll
                for (int mt = 0; mt < 2; mt++)
#pragma unroll
                    for (int nt = 0; nt < 4; nt++)
                        mma_bf16(acc[mt][nt], afr[cur][mt],
                                 bfr[cur][nt >> 1][(nt & 1) * 2],
                                 bfr[cur][nt >> 1][(nt & 1) * 2 + 1]);
            }
        }

#pragma unroll
        for (int mt = 0; mt < 2; mt++)
#pragma unroll
            for (int nt = 0; nt < 4; nt++) {
                int row0 = m0 + mbase + mt * 16 + grp4;
                int col  = nbase + nt * 8 + tg * 2;
                if (row0 < M)
                    *(__half2*)&C[((size_t)g * M + row0) * OO + col] =
                        __floats2half2_rn(acc[mt][nt][0], acc[mt][nt][1]);
                int row1 = row0 + 8;
                if (row1 < M)
                    *(__half2*)&C[((size_t)g * M + row1) * OO + col] =
                        __floats2half2_rn(acc[mt][nt][2], acc[mt][nt][3]);
            }
        __syncthreads();
    }
}

// ---------------------------------------------------------------------------
// CSR gather SpMM: one warp per output row; accumulate in regs, fused ReLU,
// single store. tmp rows are 64 halves = 32 uint32 (lane l -> cols 2l, 2l+1).
// ---------------------------------------------------------------------------
__global__ void __launch_bounds__(256)
gather_kernel(const int* __restrict__ ptr, const uint2* __restrict__ pay,
              const __half* __restrict__ tmp, float* __restrict__ z)
{
    const int row  = blockIdx.x * 8 + (threadIdx.x >> 5);
    const int lane = threadIdx.x & 31;
    if (row >= 100000) return;
    const int start = __ldg(ptr + row);
    const int end   = __ldg(ptr + row + 1);
    const uint32_t* tb = (const uint32_t*)tmp;

    float ax = 0.f, ay = 0.f;
    for (int base = start; base < end; base += 32) {
        int n = end - base;
        if (n > 32) n = 32;
        uint2 pl = make_uint2(0u, 0u);
        if (lane < n) pl = __ldg(pay + base + lane);
        int j = 0;
        for (; j + 4 <= n; j += 4) {
            uint32_t i0 = __shfl_sync(0xffffffffu, pl.x, j + 0);
            uint32_t i1 = __shfl_sync(0xffffffffu, pl.x, j + 1);
            uint32_t i2 = __shfl_sync(0xffffffffu, pl.x, j + 2);
            uint32_t i3 = __shfl_sync(0xffffffffu, pl.x, j + 3);
            float v0 = __uint_as_float(__shfl_sync(0xffffffffu, pl.y, j + 0));
            float v1 = __uint_as_float(__shfl_sync(0xffffffffu, pl.y, j + 1));
            float v2 = __uint_as_float(__shfl_sync(0xffffffffu, pl.y, j + 2));
            float v3 = __uint_as_float(__shfl_sync(0xffffffffu, pl.y, j + 3));
            uint32_t h0 = __ldg(tb + (size_t)i0 * 32 + lane);
            uint32_t h1 = __ldg(tb + (size_t)i1 * 32 + lane);
            uint32_t h2 = __ldg(tb + (size_t)i2 * 32 + lane);
            uint32_t h3 = __ldg(tb + (size_t)i3 * 32 + lane);
            float2 f0 = __half22float2(*(__half2*)&h0);
            float2 f1 = __half22float2(*(__half2*)&h1);
            float2 f2 = __half22float2(*(__half2*)&h2);
            float2 f3 = __half22float2(*(__half2*)&h3);
            ax += f0.x * v0 + f1.x * v1 + f2.x * v2 + f3.x * v3;
            ay += f0.y * v0 + f1.y * v1 + f2.y * v2 + f3.y * v3;
        }
        for (; j < n; j++) {
            uint32_t i0 = __shfl_sync(0xffffffffu, pl.x, j);
            float v0 = __uint_as_float(__shfl_sync(0xffffffffu, pl.y, j));
            uint32_t h0 = __ldg(tb + (size_t)i0 * 32 + lane);
            float2 f0 = __half22float2(*(__half2*)&h0);
            ax += f0.x * v0;
            ay += f0.y * v0;
        }
    }
    *(float2*)&z[(size_t)row * OO + lane * 2] =
        make_float2(fmaxf(ax, 0.f), fmaxf(ay, 0.f));
}

// ---------------------------------------------------------------------------
// kernel_launch
// ---------------------------------------------------------------------------
extern "C" void kernel_launch(void* const* d_in, const int* in_sizes, int n_in,
                              void* d_out, int out_size)
{
    const float* x_u  = (const float*)d_in[0];
    const float* x_v  = (const float*)d_in[1];
    const int*   srow = (const int*)d_in[2];
    const int*   scol = (const int*)d_in[3];
    const float* sval = (const float*)d_in[4];
    const float* wu   = (const float*)d_in[5];
    const float* wv   = (const float*)d_in[6];

    float* out = (float*)d_out;
    float* z_u = out;
    float* z_v = out + (size_t)NU * OO;

    __half *tmpU, *tmpV;
    unsigned char *BiU, *BiV;
    int *cnt, *ptr;
    uint2 *payU, *payV;
    cudaGetSymbolAddress((void**)&tmpU, g_tmpU);
    cudaGetSymbolAddress((void**)&tmpV, g_tmpV);
    cudaGetSymbolAddress((void**)&BiU, g_BimgU);
    cudaGetSymbolAddress((void**)&BiV, g_BimgV);
    cudaGetSymbolAddress((void**)&cnt, g_cnt);
    cudaGetSymbolAddress((void**)&ptr, g_ptr);
    cudaGetSymbolAddress((void**)&payU, g_payU);
    cudaGetSymbolAddress((void**)&payV, g_payV);

    cudaFuncSetAttribute(gemm_tc_kernel,
                         cudaFuncAttributeMaxDynamicSharedMemorySize, GT_SMEM);

    // --- CSR build ---
    cudaMemsetAsync(cnt, 0, 2 * 100000 * sizeof(int));
    cumsum_pack_kernel<<<dim3((DD * OO + 255) / 256, 2), 256>>>(wu, wv, BiU, BiV);
    hist_kernel<<<(NE_T + 255) / 256, 256>>>(srow, scol);
    scan_kernel<<<2, 1024>>>();
    scatter_kernel<<<(NE_T + 255) / 256, 256>>>(srow, scol, sval);

    // --- v side: GEMM tmpV then gather into z_u (tmpV hot in L2) ---
    gemm_tc_kernel<<<GEMM_TILES, 256, GT_SMEM>>>(x_v, BiV, tmpV, NVV);
    gather_kernel<<<12500, 256>>>(ptr, payU, tmpV, z_u);

    // --- u side ---
    gemm_tc_kernel<<<GEMM_TILES, 256, GT_SMEM>>>(x_u, BiU, tmpU, NU);
    gather_kernel<<<12500, 256>>>(ptr + 100001, payV, tmpU, z_v);
}

// round 10
// speedup vs baseline: 1.5208x; 1.5208x over previous
#include <cuda_runtime.h>
#include <cuda_fp16.h>
#include <cstdint>
#include <cstddef>

#define NU 100000
#define NVV 100000
#define DD 128
#define RR 5
#define OO 64
#define EE 640000

#define GEMM_TILES 782                 /* ceil(100000/128) */
#define SPMM_BPR   20000               /* 640000 / 32 edges per block */

// ---------------------------------------------------------------------------
// Scratch (static device globals) — tmp in fp16
// ---------------------------------------------------------------------------
__device__ __half g_tmpU[(size_t)RR * NU * OO];   // [r][n][64]
__device__ __half g_tmpV[(size_t)RR * NVV * OO];
// Pre-swizzled fp16 B images: 16KB per relation.
// Layout: row n (0..63) * 256B, 16B chunk c at (c ^ (n&7)).
__device__ unsigned char g_BimgU[RR * 16384];
__device__ unsigned char g_BimgV[RR * 16384];

// ---------------------------------------------------------------------------
// helpers
// ---------------------------------------------------------------------------
__device__ __forceinline__ uint32_t smem_u32(const void* p) {
    uint32_t a;
    asm("{ .reg .u64 t; cvta.to.shared.u64 t, %1; cvt.u32.u64 %0, t; }"
        : "=r"(a) : "l"(p));
    return a;
}
__device__ __forceinline__ void ldsm4(uint32_t addr, uint32_t& r0, uint32_t& r1,
                                      uint32_t& r2, uint32_t& r3) {
    asm volatile("ldmatrix.sync.aligned.m8n8.x4.shared.b16 {%0,%1,%2,%3}, [%4];"
                 : "=r"(r0), "=r"(r1), "=r"(r2), "=r"(r3) : "r"(addr));
}
__device__ __forceinline__ void mma_f16(float* d, const uint32_t* a,
                                        uint32_t b0, uint32_t b1) {
    asm volatile(
        "mma.sync.aligned.m16n8k16.row.col.f32.f16.f16.f32 "
        "{%0,%1,%2,%3}, {%4,%5,%6,%7}, {%8,%9}, {%0,%1,%2,%3};"
        : "+f"(d[0]), "+f"(d[1]), "+f"(d[2]), "+f"(d[3])
        : "r"(a[0]), "r"(a[1]), "r"(a[2]), "r"(a[3]), "r"(b0), "r"(b1));
}

// ---------------------------------------------------------------------------
// cumsum weights + pack swizzled fp16 B images (k = d, n = o)
// ---------------------------------------------------------------------------
__global__ void cumsum_pack_kernel(const float* __restrict__ wu,
                                   const float* __restrict__ wv,
                                   unsigned char* __restrict__ imgU,
                                   unsigned char* __restrict__ imgV)
{
    int i = blockIdx.x * blockDim.x + threadIdx.x;
    if (i >= DD * OO) return;
    const float* w    = blockIdx.y ? wv : wu;
    unsigned char* im = blockIdx.y ? imgV : imgU;
    int k = i >> 6, n = i & 63;
    uint32_t off = (uint32_t)n * 256 + ((((k >> 3) ^ (n & 7))) << 4) + (k & 7) * 2;
    float s = 0.f;
#pragma unroll
    for (int r = 0; r < RR; r++) {
        s += w[r * DD * OO + i];
        *(__half*)(im + r * 16384 + off) = __float2half_rn(s);
    }
}

// ---------------------------------------------------------------------------
// GEMM: one CTA = 128-row tile, all 5 relations. Single-pass fp16 MMA.
// SMEM: A 32KB | B 5*16KB = 112KB -> 2 CTAs/SM. 256 thr, warp tile 32x32.
// ---------------------------------------------------------------------------
#define OFF_A 0
#define OFF_B 32768
#define GT_SMEM (32768 + RR * 16384)   /* 114688 */

__global__ void __launch_bounds__(256, 2)
gemm_tc_kernel(const float* __restrict__ A,
               const unsigned char* __restrict__ Bimg,
               __half* __restrict__ C, int M)
{
    extern __shared__ unsigned char smem[];
    const int tid  = threadIdx.x;
    const int wid  = tid >> 5;
    const int lane = tid & 31;
    const int m0   = blockIdx.x * 128;

    // ---- A tile: fp32 load -> fp16 swizzled smem (once) ----
    for (int idx = tid; idx < 2048; idx += 256) {
        int m = idx >> 4, c = idx & 15, k0 = c << 3;
        float4 v0 = make_float4(0, 0, 0, 0), v1 = make_float4(0, 0, 0, 0);
        if (m0 + m < M) {
            const float* ap = A + (size_t)(m0 + m) * DD + k0;
            v0 = *(const float4*)ap;
            v1 = *(const float4*)(ap + 4);
        }
        __half2 h0 = __floats2half2_rn(v0.x, v0.y);
        __half2 h1 = __floats2half2_rn(v0.z, v0.w);
        __half2 h2 = __floats2half2_rn(v1.x, v1.y);
        __half2 h3 = __floats2half2_rn(v1.z, v1.w);
        uint32_t off = (uint32_t)m * 256 + ((c ^ (m & 7)) << 4);
        *(uint4*)(smem + OFF_A + off) =
            make_uint4(*(uint32_t*)&h0, *(uint32_t*)&h1,
                       *(uint32_t*)&h2, *(uint32_t*)&h3);
    }
    // ---- B: bulk copy all 5 pre-swizzled images (80KB) ----
    {
        const uint4* src = (const uint4*)Bimg;
        uint4* dst = (uint4*)(smem + OFF_B);
        for (int i = tid; i < (RR * 16384) / 16; i += 256) dst[i] = src[i];
    }
    __syncthreads();

    const int mbase = (wid >> 1) * 32;
    const int nbase = (wid & 1) * 32;
    const uint32_t sb = smem_u32(smem);
    const uint32_t abase = sb + OFF_A;
    const int a_m  = mbase + (lane & 15);
    const int a_cb = lane >> 4;
    const int b_n  = nbase + (lane & 7) + ((lane >> 4) & 1) * 8;
    const int b_cb = (lane >> 3) & 1;
    const int grp4 = lane >> 2, tg = lane & 3;

    for (int g = 0; g < RR; g++) {
        const uint32_t bbase = sb + OFF_B + g * 16384;

        float acc[2][4][4];
#pragma unroll
        for (int i = 0; i < 2; i++)
#pragma unroll
            for (int j = 0; j < 4; j++)
#pragma unroll
                for (int q = 0; q < 4; q++) acc[i][j][q] = 0.f;

        uint32_t afr[2][2][4], bfr[2][2][4];   // [buf][mt|pr][frag]
        auto load_frags = [&](int ks, int buf) {
            const int c = ks * 2;
#pragma unroll
            for (int mt = 0; mt < 2; mt++) {
                int m = a_m + mt * 16, cc = c + a_cb;
                uint32_t ad = abase + (uint32_t)m * 256 + ((cc ^ (m & 7)) << 4);
                ldsm4(ad, afr[buf][mt][0], afr[buf][mt][1],
                          afr[buf][mt][2], afr[buf][mt][3]);
            }
#pragma unroll
            for (int pr = 0; pr < 2; pr++) {
                int n = b_n + pr * 16, cc = c + b_cb;
                uint32_t bd = bbase + (uint32_t)n * 256 + ((cc ^ (n & 7)) << 4);
                ldsm4(bd, bfr[buf][pr][0], bfr[buf][pr][1],
                          bfr[buf][pr][2], bfr[buf][pr][3]);
            }
        };
        load_frags(0, 0);
#pragma unroll
        for (int ks = 0; ks < 8; ks++) {
            const int cur = ks & 1;
            if (ks < 7) load_frags(ks + 1, cur ^ 1);
#pragma unroll
            for (int mt = 0; mt < 2; mt++)
#pragma unroll
                for (int nt = 0; nt < 4; nt++)
                    mma_f16(acc[mt][nt], afr[cur][mt],
                            bfr[cur][nt >> 1][(nt & 1) * 2],
                            bfr[cur][nt >> 1][(nt & 1) * 2 + 1]);
        }

        // ---- epilogue: fp16 half2 stores ----
#pragma unroll
        for (int mt = 0; mt < 2; mt++)
#pragma unroll
            for (int nt = 0; nt < 4; nt++) {
                int row0 = m0 + mbase + mt * 16 + grp4;
                int col  = nbase + nt * 8 + tg * 2;
                if (row0 < M)
                    *(__half2*)&C[((size_t)g * M + row0) * OO + col] =
                        __floats2half2_rn(acc[mt][nt][0], acc[mt][nt][1]);
                int row1 = row0 + 8;
                if (row1 < M)
                    *(__half2*)&C[((size_t)g * M + row1) * OO + col] =
                        __floats2half2_rn(acc[mt][nt][2], acc[mt][nt][3]);
            }
        // no sync needed: smem is read-only across relations
    }
}

// ---------------------------------------------------------------------------
// SpMM: 16 lanes/edge, 2 edges/group, fp16 gathers, fp32 red.v4 scatter.
// block = 256 threads = 32 edges. grid = (20000, RR).
// ---------------------------------------------------------------------------
__global__ void __launch_bounds__(256)
spmm_kernel(const int* __restrict__ rows, const int* __restrict__ cols,
            const float* __restrict__ vals, const __half* __restrict__ tmp,
            float* __restrict__ z)
{
    const int rel = blockIdx.y;
    const int grp = threadIdx.x >> 4;
    const int l16 = threadIdx.x & 15;
    const int e   = blockIdx.x * 32 + grp * 2;
    const size_t eo = (size_t)rel * EE + e;

    int2 rw = make_int2(0, 0), cl = make_int2(0, 0);
    float2 vv = make_float2(0.f, 0.f);
    if (l16 == 0) {
        rw = *(const int2*)(rows + eo);
        cl = *(const int2*)(cols + eo);
        vv = *(const float2*)(vals + eo);
    }
    int   row0 = __shfl_sync(0xffffffffu, rw.x, 0, 16);
    int   row1 = __shfl_sync(0xffffffffu, rw.y, 0, 16);
    int   col0 = __shfl_sync(0xffffffffu, cl.x, 0, 16);
    int   col1 = __shfl_sync(0xffffffffu, cl.y, 0, 16);
    float v0   = __shfl_sync(0xffffffffu, vv.x, 0, 16);
    float v1   = __shfl_sync(0xffffffffu, vv.y, 0, 16);

    const uint2* tb = (const uint2*)(tmp + (size_t)rel * 100000 * OO);
    uint2 t0 = __ldg(tb + (size_t)col0 * 16 + l16);
    uint2 t1 = __ldg(tb + (size_t)col1 * 16 + l16);

    float2 a0 = __half22float2(*(__half2*)&t0.x);
    float2 a1 = __half22float2(*(__half2*)&t0.y);
    float2 b0 = __half22float2(*(__half2*)&t1.x);
    float2 b1 = __half22float2(*(__half2*)&t1.y);

    float* d0 = z + (size_t)row0 * OO + (l16 << 2);
    float* d1 = z + (size_t)row1 * OO + (l16 << 2);
    asm volatile("red.global.add.v4.f32 [%0], {%1, %2, %3, %4};"
                 :: "l"(d0), "f"(a0.x * v0), "f"(a0.y * v0),
                    "f"(a1.x * v0), "f"(a1.y * v0)
                 : "memory");
    asm volatile("red.global.add.v4.f32 [%0], {%1, %2, %3, %4};"
                 :: "l"(d1), "f"(b0.x * v1), "f"(b0.y * v1),
                    "f"(b1.x * v1), "f"(b1.y * v1)
                 : "memory");
}

// ---------------------------------------------------------------------------
// zero / relu
// ---------------------------------------------------------------------------
__global__ void zero_kernel(float4* __restrict__ p, int n4)
{
    int i = blockIdx.x * blockDim.x + threadIdx.x;
    if (i < n4) p[i] = make_float4(0.f, 0.f, 0.f, 0.f);
}
__global__ void relu_kernel(float4* __restrict__ p, int n4)
{
    int i = blockIdx.x * blockDim.x + threadIdx.x;
    if (i < n4) {
        float4 v = p[i];
        v.x = fmaxf(v.x, 0.f); v.y = fmaxf(v.y, 0.f);
        v.z = fmaxf(v.z, 0.f); v.w = fmaxf(v.w, 0.f);
        p[i] = v;
    }
}

// ---------------------------------------------------------------------------
// kernel_launch
// ---------------------------------------------------------------------------
extern "C" void kernel_launch(void* const* d_in, const int* in_sizes, int n_in,
                              void* d_out, int out_size)
{
    const float* x_u  = (const float*)d_in[0];
    const float* x_v  = (const float*)d_in[1];
    const int*   srow = (const int*)d_in[2];
    const int*   scol = (const int*)d_in[3];
    const float* sval = (const float*)d_in[4];
    const float* wu   = (const float*)d_in[5];
    const float* wv   = (const float*)d_in[6];

    float* out = (float*)d_out;
    float* z_u = out;
    float* z_v = out + (size_t)NU * OO;

    __half *tmpU, *tmpV;
    unsigned char *BiU, *BiV;
    cudaGetSymbolAddress((void**)&tmpU, g_tmpU);
    cudaGetSymbolAddress((void**)&tmpV, g_tmpV);
    cudaGetSymbolAddress((void**)&BiU, g_BimgU);
    cudaGetSymbolAddress((void**)&BiV, g_BimgV);

    cudaFuncSetAttribute(gemm_tc_kernel,
                         cudaFuncAttributeMaxDynamicSharedMemorySize, GT_SMEM);

    const int n4 = (NU * OO + NVV * OO) / 4;
    zero_kernel<<<(n4 + 255) / 256, 256>>>((float4*)out, n4);

    cumsum_pack_kernel<<<dim3((DD * OO + 255) / 256, 2), 256>>>(wu, wv, BiU, BiV);

    // v side: GEMM tmpV then scatter into z_u (tmpV hot in L2)
    gemm_tc_kernel<<<GEMM_TILES, 256, GT_SMEM>>>(x_v, BiV, tmpV, NVV);
    spmm_kernel<<<dim3(SPMM_BPR, RR), 256>>>(srow, scol, sval, tmpV, z_u);

    // u side
    gemm_tc_kernel<<<GEMM_TILES, 256, GT_SMEM>>>(x_u, BiU, tmpU, NU);
    spmm_kernel<<<dim3(SPMM_BPR, RR), 256>>>(scol, srow, sval, tmpU, z_v);

    relu_kernel<<<(n4 + 255) / 256, 256>>>((float4*)out, n4);
}

// round 11
// speedup vs baseline: 1.5570x; 1.0238x over previous
#include <cuda_runtime.h>
#include <cuda_fp16.h>
#include <cstdint>
#include <cstddef>

#define NU 100000
#define NVV 100000
#define DD 128
#define RR 5
#define OO 64
#define EE 640000

#define GEMM_TILES 782                 /* ceil(100000/128) */
#define SPMM_BPR   20000               /* 640000 / 32 edges per block */

// ---------------------------------------------------------------------------
// Scratch (static device globals) — tmp in fp16
// ---------------------------------------------------------------------------
__device__ __half g_tmpU[(size_t)RR * NU * OO];   // [r][n][64]
__device__ __half g_tmpV[(size_t)RR * NVV * OO];
// Pre-swizzled fp16 B images: 16KB per relation.
// Layout: row n (0..63) * 256B, 16B chunk c at (c ^ (n&7)).
__device__ unsigned char g_BimgU[RR * 16384];
__device__ unsigned char g_BimgV[RR * 16384];

// ---------------------------------------------------------------------------
// helpers
// ---------------------------------------------------------------------------
__device__ __forceinline__ uint32_t smem_u32(const void* p) {
    uint32_t a;
    asm("{ .reg .u64 t; cvta.to.shared.u64 t, %1; cvt.u32.u64 %0, t; }"
        : "=r"(a) : "l"(p));
    return a;
}
__device__ __forceinline__ void ldsm4(uint32_t addr, uint32_t& r0, uint32_t& r1,
                                      uint32_t& r2, uint32_t& r3) {
    asm volatile("ldmatrix.sync.aligned.m8n8.x4.shared.b16 {%0,%1,%2,%3}, [%4];"
                 : "=r"(r0), "=r"(r1), "=r"(r2), "=r"(r3) : "r"(addr));
}
__device__ __forceinline__ void mma_f16(float* d, const uint32_t* a,
                                        uint32_t b0, uint32_t b1) {
    asm volatile(
        "mma.sync.aligned.m16n8k16.row.col.f32.f16.f16.f32 "
        "{%0,%1,%2,%3}, {%4,%5,%6,%7}, {%8,%9}, {%0,%1,%2,%3};"
        : "+f"(d[0]), "+f"(d[1]), "+f"(d[2]), "+f"(d[3])
        : "r"(a[0]), "r"(a[1]), "r"(a[2]), "r"(a[3]), "r"(b0), "r"(b1));
}

// ---------------------------------------------------------------------------
// cumsum weights + pack swizzled fp16 B images (k = d, n = o)
// ---------------------------------------------------------------------------
__global__ void cumsum_pack_kernel(const float* __restrict__ wu,
                                   const float* __restrict__ wv,
                                   unsigned char* __restrict__ imgU,
                                   unsigned char* __restrict__ imgV)
{
    int i = blockIdx.x * blockDim.x + threadIdx.x;
    if (i >= DD * OO) return;
    const float* w    = blockIdx.y ? wv : wu;
    unsigned char* im = blockIdx.y ? imgV : imgU;
    int k = i >> 6, n = i & 63;
    uint32_t off = (uint32_t)n * 256 + ((((k >> 3) ^ (n & 7))) << 4) + (k & 7) * 2;
    float s = 0.f;
#pragma unroll
    for (int r = 0; r < RR; r++) {
        s += w[r * DD * OO + i];
        *(__half*)(im + r * 16384 + off) = __float2half_rn(s);
    }
}

// ---------------------------------------------------------------------------
// GEMM: one CTA = 128-row tile, all 5 relations. Single-pass fp16 MMA.
// SMEM: A 32KB | B 5*16KB = 112KB -> 2 CTAs/SM. 256 thr, warp tile 32x32.
// ---------------------------------------------------------------------------
#define OFF_A 0
#define OFF_B 32768
#define GT_SMEM (32768 + RR * 16384)   /* 114688 */

__global__ void __launch_bounds__(256, 2)
gemm_tc_kernel(const float* __restrict__ A,
               const unsigned char* __restrict__ Bimg,
               __half* __restrict__ C, int M)
{
    extern __shared__ unsigned char smem[];
    const int tid  = threadIdx.x;
    const int wid  = tid >> 5;
    const int lane = tid & 31;
    const int m0   = blockIdx.x * 128;

    // ---- A tile: fp32 load -> fp16 swizzled smem (once) ----
    for (int idx = tid; idx < 2048; idx += 256) {
        int m = idx >> 4, c = idx & 15, k0 = c << 3;
        float4 v0 = make_float4(0, 0, 0, 0), v1 = make_float4(0, 0, 0, 0);
        if (m0 + m < M) {
            const float* ap = A + (size_t)(m0 + m) * DD + k0;
            v0 = *(const float4*)ap;
            v1 = *(const float4*)(ap + 4);
        }
        __half2 h0 = __floats2half2_rn(v0.x, v0.y);
        __half2 h1 = __floats2half2_rn(v0.z, v0.w);
        __half2 h2 = __floats2half2_rn(v1.x, v1.y);
        __half2 h3 = __floats2half2_rn(v1.z, v1.w);
        uint32_t off = (uint32_t)m * 256 + ((c ^ (m & 7)) << 4);
        *(uint4*)(smem + OFF_A + off) =
            make_uint4(*(uint32_t*)&h0, *(uint32_t*)&h1,
                       *(uint32_t*)&h2, *(uint32_t*)&h3);
    }
    // ---- B: bulk copy all 5 pre-swizzled images (80KB) ----
    {
        const uint4* src = (const uint4*)Bimg;
        uint4* dst = (uint4*)(smem + OFF_B);
        for (int i = tid; i < (RR * 16384) / 16; i += 256) dst[i] = src[i];
    }
    __syncthreads();

    const int mbase = (wid >> 1) * 32;
    const int nbase = (wid & 1) * 32;
    const uint32_t sb = smem_u32(smem);
    const uint32_t abase = sb + OFF_A;
    const int a_m  = mbase + (lane & 15);
    const int a_cb = lane >> 4;
    const int b_n  = nbase + (lane & 7) + ((lane >> 4) & 1) * 8;
    const int b_cb = (lane >> 3) & 1;
    const int grp4 = lane >> 2, tg = lane & 3;

    for (int g = 0; g < RR; g++) {
        const uint32_t bbase = sb + OFF_B + g * 16384;

        float acc[2][4][4];
#pragma unroll
        for (int i = 0; i < 2; i++)
#pragma unroll
            for (int j = 0; j < 4; j++)
#pragma unroll
                for (int q = 0; q < 4; q++) acc[i][j][q] = 0.f;

        uint32_t afr[2][2][4], bfr[2][2][4];   // [buf][mt|pr][frag]
        auto load_frags = [&](int ks, int buf) {
            const int c = ks * 2;
#pragma unroll
            for (int mt = 0; mt < 2; mt++) {
                int m = a_m + mt * 16, cc = c + a_cb;
                uint32_t ad = abase + (uint32_t)m * 256 + ((cc ^ (m & 7)) << 4);
                ldsm4(ad, afr[buf][mt][0], afr[buf][mt][1],
                          afr[buf][mt][2], afr[buf][mt][3]);
            }
#pragma unroll
            for (int pr = 0; pr < 2; pr++) {
                int n = b_n + pr * 16, cc = c + b_cb;
                uint32_t bd = bbase + (uint32_t)n * 256 + ((cc ^ (n & 7)) << 4);
                ldsm4(bd, bfr[buf][pr][0], bfr[buf][pr][1],
                          bfr[buf][pr][2], bfr[buf][pr][3]);
            }
        };
        load_frags(0, 0);
#pragma unroll
        for (int ks = 0; ks < 8; ks++) {
            const int cur = ks & 1;
            if (ks < 7) load_frags(ks + 1, cur ^ 1);
#pragma unroll
            for (int mt = 0; mt < 2; mt++)
#pragma unroll
                for (int nt = 0; nt < 4; nt++)
                    mma_f16(acc[mt][nt], afr[cur][mt],
                            bfr[cur][nt >> 1][(nt & 1) * 2],
                            bfr[cur][nt >> 1][(nt & 1) * 2 + 1]);
        }

        // ---- epilogue: fp16 half2 stores ----
#pragma unroll
        for (int mt = 0; mt < 2; mt++)
#pragma unroll
            for (int nt = 0; nt < 4; nt++) {
                int row0 = m0 + mbase + mt * 16 + grp4;
                int col  = nbase + nt * 8 + tg * 2;
                if (row0 < M)
                    *(__half2*)&C[((size_t)g * M + row0) * OO + col] =
                        __floats2half2_rn(acc[mt][nt][0], acc[mt][nt][1]);
                int row1 = row0 + 8;
                if (row1 < M)
                    *(__half2*)&C[((size_t)g * M + row1) * OO + col] =
                        __floats2half2_rn(acc[mt][nt][2], acc[mt][nt][3]);
            }
        // no sync needed: smem is read-only across relations
    }
}

// ---------------------------------------------------------------------------
// SpMM: 16 lanes/edge, 2 edges/group, fp16 gathers, fp32 red.v4 scatter.
// block = 256 threads = 32 edges. grid = (20000, RR).
// ---------------------------------------------------------------------------
__global__ void __launch_bounds__(256)
spmm_kernel(const int* __restrict__ rows, const int* __restrict__ cols,
            const float* __restrict__ vals, const __half* __restrict__ tmp,
            float* __restrict__ z)
{
    const int rel = blockIdx.y;
    const int grp = threadIdx.x >> 4;
    const int l16 = threadIdx.x & 15;
    const int e   = blockIdx.x * 32 + grp * 2;
    const size_t eo = (size_t)rel * EE + e;

    int2 rw = make_int2(0, 0), cl = make_int2(0, 0);
    float2 vv = make_float2(0.f, 0.f);
    if (l16 == 0) {
        rw = *(const int2*)(rows + eo);
        cl = *(const int2*)(cols + eo);
        vv = *(const float2*)(vals + eo);
    }
    int   row0 = __shfl_sync(0xffffffffu, rw.x, 0, 16);
    int   row1 = __shfl_sync(0xffffffffu, rw.y, 0, 16);
    int   col0 = __shfl_sync(0xffffffffu, cl.x, 0, 16);
    int   col1 = __shfl_sync(0xffffffffu, cl.y, 0, 16);
    float v0   = __shfl_sync(0xffffffffu, vv.x, 0, 16);
    float v1   = __shfl_sync(0xffffffffu, vv.y, 0, 16);

    const uint2* tb = (const uint2*)(tmp + (size_t)rel * 100000 * OO);
    uint2 t0 = __ldg(tb + (size_t)col0 * 16 + l16);
    uint2 t1 = __ldg(tb + (size_t)col1 * 16 + l16);

    float2 a0 = __half22float2(*(__half2*)&t0.x);
    float2 a1 = __half22float2(*(__half2*)&t0.y);
    float2 b0 = __half22float2(*(__half2*)&t1.x);
    float2 b1 = __half22float2(*(__half2*)&t1.y);

    float* d0 = z + (size_t)row0 * OO + (l16 << 2);
    float* d1 = z + (size_t)row1 * OO + (l16 << 2);
    asm volatile("red.global.add.v4.f32 [%0], {%1, %2, %3, %4};"
                 :: "l"(d0), "f"(a0.x * v0), "f"(a0.y * v0),
                    "f"(a1.x * v0), "f"(a1.y * v0)
                 : "memory");
    asm volatile("red.global.add.v4.f32 [%0], {%1, %2, %3, %4};"
                 :: "l"(d1), "f"(b0.x * v1), "f"(b0.y * v1),
                    "f"(b1.x * v1), "f"(b1.y * v1)
                 : "memory");
}

// ---------------------------------------------------------------------------
// zero / relu (range versions so halves can be scheduled independently)
// ---------------------------------------------------------------------------
__global__ void zero_kernel(float4* __restrict__ p, int n4)
{
    int i = blockIdx.x * blockDim.x + threadIdx.x;
    if (i < n4) p[i] = make_float4(0.f, 0.f, 0.f, 0.f);
}
__global__ void relu_kernel(float4* __restrict__ p, int n4)
{
    int i = blockIdx.x * blockDim.x + threadIdx.x;
    if (i < n4) {
        float4 v = p[i];
        v.x = fmaxf(v.x, 0.f); v.y = fmaxf(v.y, 0.f);
        v.z = fmaxf(v.z, 0.f); v.w = fmaxf(v.w, 0.f);
        p[i] = v;
    }
}

// ---------------------------------------------------------------------------
// kernel_launch — forked-stream schedule:
//   cumsum -> [gemmV || zero(out)] -> [spmmV || gemmU] -> [spmmU || relu_u]
//   -> relu_v ; join.
// Stream/events created once on the first (uncaptured) call.
// ---------------------------------------------------------------------------
extern "C" void kernel_launch(void* const* d_in, const int* in_sizes, int n_in,
                              void* d_out, int out_size)
{
    const float* x_u  = (const float*)d_in[0];
    const float* x_v  = (const float*)d_in[1];
    const int*   srow = (const int*)d_in[2];
    const int*   scol = (const int*)d_in[3];
    const float* sval = (const float*)d_in[4];
    const float* wu   = (const float*)d_in[5];
    const float* wv   = (const float*)d_in[6];

    float* out = (float*)d_out;
    float* z_u = out;
    float* z_v = out + (size_t)NU * OO;

    __half *tmpU, *tmpV;
    unsigned char *BiU, *BiV;
    cudaGetSymbolAddress((void**)&tmpU, g_tmpU);
    cudaGetSymbolAddress((void**)&tmpV, g_tmpV);
    cudaGetSymbolAddress((void**)&BiU, g_BimgU);
    cudaGetSymbolAddress((void**)&BiV, g_BimgV);

    static cudaStream_t s2 = nullptr;
    static cudaEvent_t evFork, evZero, evGemmU, evZu, evJoin;
    if (!s2) {
        cudaStreamCreateWithFlags(&s2, cudaStreamNonBlocking);
        cudaEventCreateWithFlags(&evFork,  cudaEventDisableTiming);
        cudaEventCreateWithFlags(&evZero,  cudaEventDisableTiming);
        cudaEventCreateWithFlags(&evGemmU, cudaEventDisableTiming);
        cudaEventCreateWithFlags(&evZu,    cudaEventDisableTiming);
        cudaEventCreateWithFlags(&evJoin,  cudaEventDisableTiming);
        cudaFuncSetAttribute(gemm_tc_kernel,
                             cudaFuncAttributeMaxDynamicSharedMemorySize,
                             GT_SMEM);
    }

    const int n4 = (NU * OO + NVV * OO) / 4;        // 3.2M float4

    // stage 0: cumsum (stream 0), then fork
    cumsum_pack_kernel<<<dim3((DD * OO + 255) / 256, 2), 256>>>(wu, wv, BiU, BiV);
    cudaEventRecord(evFork, 0);
    cudaStreamWaitEvent(s2, evFork, 0);

    // stage 1: gemmV (stream 0)  ||  zero whole out (s2)
    zero_kernel<<<(n4 + 255) / 256, 256, 0, s2>>>((float4*)out, n4);
    gemm_tc_kernel<<<GEMM_TILES, 256, GT_SMEM>>>(x_v, BiV, tmpV, NVV);
    cudaEventRecord(evZero, s2);
    cudaStreamWaitEvent(0, evZero, 0);       // spmmV needs z_u zeroed
    cudaEventRecord(evFork, 0);              // gemmV + zero both done here
    cudaStreamWaitEvent(s2, evFork, 0);

    // stage 2: spmmV -> z_u (stream 0)  ||  gemmU -> tmpU (s2)
    gemm_tc_kernel<<<GEMM_TILES, 256, GT_SMEM, s2>>>(x_u, BiU, tmpU, NU);
    spmm_kernel<<<dim3(SPMM_BPR, RR), 256>>>(srow, scol, sval, tmpV, z_u);
    cudaEventRecord(evGemmU, s2);
    cudaStreamWaitEvent(0, evGemmU, 0);      // spmmU needs tmpU
    cudaEventRecord(evZu, 0);                // z_u final after spmmV
    cudaStreamWaitEvent(s2, evZu, 0);

    // stage 3: spmmU -> z_v (stream 0)  ||  relu z_u (s2)
    relu_kernel<<<(n4 / 2 + 255) / 256, 256, 0, s2>>>((float4*)z_u, n4 / 2);
    spmm_kernel<<<dim3(SPMM_BPR, RR), 256>>>(scol, srow, sval, tmpU, z_v);

    // stage 4: relu z_v (stream 0); join s2
    relu_kernel<<<(n4 / 2 + 255) / 256, 256>>>((float4*)z_v, n4 / 2);
    cudaEventRecord(evJoin, s2);
    cudaStreamWaitEvent(0, evJoin, 0);
}